// round 3
// baseline (speedup 1.0000x reference)
#include <cuda_runtime.h>
#include <cuda_fp16.h>
#include <cstdint>

#define NUM_E 8
#define DIM_H 2880
#define DIM_I 2880
#define DIM_T 1024
#define DIM_F 5760
#define NGRP  90

// scratch (static device globals: allowed; no runtime allocation)
__device__ __half g_xh_hi[DIM_T * DIM_H];
__device__ __half g_xh_lo[DIM_T * DIM_H];
__device__ __half g_act_hi[(size_t)NUM_E * DIM_T * DIM_I];
__device__ __half g_act_lo[(size_t)NUM_E * DIM_T * DIM_I];
__device__ float  g_oute[(size_t)NUM_E * DIM_T * DIM_H];

// fp4 e2m1 value table as fp16 bit patterns: {0,.5,1,1.5,2,3,4,6, -...}
__constant__ unsigned short c_fp4[16] = {
    0x0000, 0x3800, 0x3C00, 0x3E00, 0x4000, 0x4200, 0x4400, 0x4600,
    0x8000, 0xB800, 0xBC00, 0xBE00, 0xC000, 0xC200, 0xC400, 0xC600};

__global__ void k_convert(const float4* __restrict__ x, int n4) {
    int i = blockIdx.x * blockDim.x + threadIdx.x;
    if (i < n4) {
        float4 v = x[i];
        __half h[4], l[4];
        float f[4] = {v.x, v.y, v.z, v.w};
#pragma unroll
        for (int j = 0; j < 4; j++) {
            h[j] = __float2half_rn(f[j]);
            l[j] = __float2half_rn(f[j] - __half2float(h[j]));
        }
        reinterpret_cast<__half2*>(g_xh_hi)[2 * i]     = __halves2half2(h[0], h[1]);
        reinterpret_cast<__half2*>(g_xh_hi)[2 * i + 1] = __halves2half2(h[2], h[3]);
        reinterpret_cast<__half2*>(g_xh_lo)[2 * i]     = __halves2half2(l[0], l[1]);
        reinterpret_cast<__half2*>(g_xh_lo)[2 * i + 1] = __halves2half2(l[2], l[3]);
    }
}

__global__ void k_reduce(float* __restrict__ out, int n4) {
    int i = blockIdx.x * blockDim.x + threadIdx.x;
    if (i < n4) {
        const float4* src = reinterpret_cast<const float4*>(g_oute);
        float4 s = src[i];
#pragma unroll
        for (int e = 1; e < NUM_E; e++) {
            float4 v = src[(size_t)e * n4 + i];
            s.x += v.x; s.y += v.y; s.z += v.z; s.w += v.w;
        }
        reinterpret_cast<float4*>(out)[i] = s;
    }
}

// ---------------------------------------------------------------------------
// Fused GEMM, inline MXFP4 dequant of B (exact in fp16), split-precision A
// (hi+lo fp16 pair => ~fp32-accurate A), fp16 mma.sync, double-buffered.
// EPI==1: C = X @ Wgu^T (+bias) -> GLU -> g_act_{hi,lo} (fp16 pair)  [N=5760]
// EPI==2: C = act @ Wd^T (+bias) * rw  -> g_oute (fp32)              [N=2880]
// ---------------------------------------------------------------------------
#define LDS 40
#define SMEM_BYTES (3 * 2 * 128 * LDS * 2 + 256 * 4)

template <int EPI>
__global__ __launch_bounds__(256) void gemm_glu(const int* __restrict__ Bblocks,
                                                const int* __restrict__ Bscales,
                                                const float* __restrict__ bias,
                                                const float* __restrict__ rw) {
    constexpr int N  = (EPI == 1) ? DIM_F : DIM_H;
    constexpr int K  = 2880;
    constexpr int KT = K / 32;
    constexpr int M  = DIM_T;

    const int e    = blockIdx.z;
    const int n0   = blockIdx.x * 128;
    const int m0   = blockIdx.y * 128;
    const int tid  = threadIdx.x;
    const int lane = tid & 31;
    const int wid  = tid >> 5;
    const int wm   = wid >> 2;  // 0..1  (M warps)
    const int wn   = wid & 3;   // 0..3  (N warps)

    extern __shared__ __align__(16) char smem_raw[];
    __half* AsH = reinterpret_cast<__half*>(smem_raw);
    __half* AsL = AsH + 2 * 128 * LDS;
    __half* Bs  = AsL + 2 * 128 * LDS;
    __half2* lut = reinterpret_cast<__half2*>(Bs + 2 * 128 * LDS);

#define SM_AH(s, r, c) AsH[((s)*128 + (r)) * LDS + (c)]
#define SM_AL(s, r, c) AsL[((s)*128 + (r)) * LDS + (c)]
#define SM_B(s, r, c)  Bs[((s)*128 + (r)) * LDS + (c)]

    // 256-entry byte -> (lo_nib, hi_nib) fp16 pair LUT
    lut[tid] = __halves2half2(__ushort_as_half(c_fp4[tid & 15]),
                              __ushort_as_half(c_fp4[(tid >> 4) & 15]));

    const __half* AgH = (EPI == 1) ? g_xh_hi : (g_act_hi + (size_t)e * M * K);
    const __half* AgL = (EPI == 1) ? g_xh_lo : (g_act_lo + (size_t)e * M * K);

    // A loader mapping: 16B per thread per 64 rows
    const int ar = tid >> 2;
    const int ac = (tid & 3) * 8;
    // B loader mapping: one half-group (8 int32 = 8 packed bytes = 16 weights)
    const int br = tid >> 1;
    const int bh = tid & 1;
    int bn = n0 + br;
    if (bn > N - 1) bn = N - 1;
    const size_t brow_off = ((size_t)e * N + bn) * NGRP;

    float acc[4][4][4];
#pragma unroll
    for (int i = 0; i < 4; i++)
#pragma unroll
        for (int j = 0; j < 4; j++)
#pragma unroll
            for (int c = 0; c < 4; c++) acc[i][j][c] = 0.f;

    // ---- prologue: stage 0 ----
    int4 v0, v1;
    int sc;
    {
#pragma unroll
        for (int rr = 0; rr < 128; rr += 64) {
            unsigned sa = (unsigned)__cvta_generic_to_shared(&SM_AH(0, ar + rr, ac));
            const __half* g = AgH + (size_t)(m0 + ar + rr) * K + ac;
            asm volatile("cp.async.cg.shared.global [%0],[%1],16;\n" ::"r"(sa), "l"(g));
            unsigned sl = (unsigned)__cvta_generic_to_shared(&SM_AL(0, ar + rr, ac));
            const __half* gl = AgL + (size_t)(m0 + ar + rr) * K + ac;
            asm volatile("cp.async.cg.shared.global [%0],[%1],16;\n" ::"r"(sl), "l"(gl));
        }
        asm volatile("cp.async.commit_group;\n");
        const int4* p = reinterpret_cast<const int4*>(Bblocks) + (brow_off * 4 + bh * 2);
        v0 = p[0];
        v1 = p[1];
        sc = Bscales[brow_off];
    }
    __syncthreads();  // lut ready
    {
        __half2 s2 = __half2half2(__ushort_as_half((unsigned short)((sc - 112) << 10)));
        __half2 o[8];
        int bb[8] = {v0.x, v0.y, v0.z, v0.w, v1.x, v1.y, v1.z, v1.w};
#pragma unroll
        for (int j = 0; j < 8; j++) o[j] = __hmul2(lut[bb[j] & 255], s2);
        int4* dst = reinterpret_cast<int4*>(&SM_B(0, br, bh * 16));
        dst[0] = *reinterpret_cast<const int4*>(&o[0]);
        dst[1] = *reinterpret_cast<const int4*>(&o[4]);
    }
    asm volatile("cp.async.wait_group 0;\n");
    __syncthreads();

    // ---- main loop ----
#pragma unroll 1
    for (int kt = 0; kt < KT; ++kt) {
        const int cur = kt & 1;
        const int nxt = cur ^ 1;
        int4 nv0, nv1;
        int nsc = 127;
        if (kt + 1 < KT) {
#pragma unroll
            for (int rr = 0; rr < 128; rr += 64) {
                unsigned sa = (unsigned)__cvta_generic_to_shared(&SM_AH(nxt, ar + rr, ac));
                const __half* g = AgH + (size_t)(m0 + ar + rr) * K + (kt + 1) * 32 + ac;
                asm volatile("cp.async.cg.shared.global [%0],[%1],16;\n" ::"r"(sa), "l"(g));
                unsigned sl = (unsigned)__cvta_generic_to_shared(&SM_AL(nxt, ar + rr, ac));
                const __half* gl = AgL + (size_t)(m0 + ar + rr) * K + (kt + 1) * 32 + ac;
                asm volatile("cp.async.cg.shared.global [%0],[%1],16;\n" ::"r"(sl), "l"(gl));
            }
            asm volatile("cp.async.commit_group;\n");
            const int4* p =
                reinterpret_cast<const int4*>(Bblocks) + ((brow_off + kt + 1) * 4 + bh * 2);
            nv0 = p[0];
            nv1 = p[1];
            nsc = Bscales[brow_off + kt + 1];
        } else {
            nv0 = v0;  // dead
            nv1 = v1;
        }
        // compute on cur
#pragma unroll
        for (int kk = 0; kk < 2; ++kk) {
            unsigned bfr[4][2];
            {
                int row = wn * 32 + (lane & 7);
                int col = kk * 16 + ((lane >> 3) & 1) * 8;
#pragma unroll
                for (int ni = 0; ni < 4; ni++) {
                    unsigned sa =
                        (unsigned)__cvta_generic_to_shared(&SM_B(cur, row + ni * 8, col));
                    asm volatile("ldmatrix.sync.aligned.m8n8.x2.shared.b16 {%0,%1},[%2];"
                                 : "=r"(bfr[ni][0]), "=r"(bfr[ni][1])
                                 : "r"(sa));
                }
            }
            int arow = wm * 64 + (lane & 15);
            int acol = kk * 16 + (lane >> 4) * 8;
#pragma unroll
            for (int mi = 0; mi < 4; mi++) {
                unsigned ah[4], al[4];
                unsigned sh =
                    (unsigned)__cvta_generic_to_shared(&SM_AH(cur, arow + mi * 16, acol));
                asm volatile("ldmatrix.sync.aligned.m8n8.x4.shared.b16 {%0,%1,%2,%3},[%4];"
                             : "=r"(ah[0]), "=r"(ah[1]), "=r"(ah[2]), "=r"(ah[3])
                             : "r"(sh));
                unsigned sl2 =
                    (unsigned)__cvta_generic_to_shared(&SM_AL(cur, arow + mi * 16, acol));
                asm volatile("ldmatrix.sync.aligned.m8n8.x4.shared.b16 {%0,%1,%2,%3},[%4];"
                             : "=r"(al[0]), "=r"(al[1]), "=r"(al[2]), "=r"(al[3])
                             : "r"(sl2));
#pragma unroll
                for (int ni = 0; ni < 4; ni++) {
                    asm volatile(
                        "mma.sync.aligned.m16n8k16.row.col.f32.f16.f16.f32 "
                        "{%0,%1,%2,%3},{%4,%5,%6,%7},{%8,%9},{%0,%1,%2,%3};"
                        : "+f"(acc[mi][ni][0]), "+f"(acc[mi][ni][1]), "+f"(acc[mi][ni][2]),
                          "+f"(acc[mi][ni][3])
                        : "r"(ah[0]), "r"(ah[1]), "r"(ah[2]), "r"(ah[3]),
                          "r"(bfr[ni][0]), "r"(bfr[ni][1]));
                    asm volatile(
                        "mma.sync.aligned.m16n8k16.row.col.f32.f16.f16.f32 "
                        "{%0,%1,%2,%3},{%4,%5,%6,%7},{%8,%9},{%0,%1,%2,%3};"
                        : "+f"(acc[mi][ni][0]), "+f"(acc[mi][ni][1]), "+f"(acc[mi][ni][2]),
                          "+f"(acc[mi][ni][3])
                        : "r"(al[0]), "r"(al[1]), "r"(al[2]), "r"(al[3]),
                          "r"(bfr[ni][0]), "r"(bfr[ni][1]));
                }
            }
        }
        if (kt + 1 < KT) {
            __half2 s2 =
                __half2half2(__ushort_as_half((unsigned short)((nsc - 112) << 10)));
            __half2 o[8];
            int bb[8] = {nv0.x, nv0.y, nv0.z, nv0.w, nv1.x, nv1.y, nv1.z, nv1.w};
#pragma unroll
            for (int j = 0; j < 8; j++) o[j] = __hmul2(lut[bb[j] & 255], s2);
            int4* dst = reinterpret_cast<int4*>(&SM_B(nxt, br, bh * 16));
            dst[0] = *reinterpret_cast<const int4*>(&o[0]);
            dst[1] = *reinterpret_cast<const int4*>(&o[4]);
            asm volatile("cp.async.wait_group 0;\n");
            v0 = nv0;
            v1 = nv1;
        }
        __syncthreads();
    }

    // ---- epilogue ----
    if (EPI == 1) {
#pragma unroll
        for (int mi = 0; mi < 4; mi++)
#pragma unroll
            for (int ni = 0; ni < 4; ni++) {
                int f = n0 + wn * 32 + ni * 8 + (lane & 3) * 2;
                float bg = bias[(size_t)e * N + f];
                float bu = bias[(size_t)e * N + f + 1];
#pragma unroll
                for (int hh = 0; hh < 2; hh++) {
                    int t = m0 + wm * 64 + mi * 16 + (lane >> 2) + hh * 8;
                    float gte = fminf(acc[mi][ni][hh * 2] + bg, 7.0f);
                    float up = fminf(fmaxf(acc[mi][ni][hh * 2 + 1] + bu, -7.0f), 7.0f);
                    float glu = gte / (1.0f + expf(-1.702f * gte));
                    float a = (up + 1.0f) * glu;
                    __half hv = __float2half_rn(a);
                    size_t idx = ((size_t)e * M + t) * DIM_I + (f >> 1);
                    g_act_hi[idx] = hv;
                    g_act_lo[idx] = __float2half_rn(a - __half2float(hv));
                }
            }
    } else {
#pragma unroll
        for (int mi = 0; mi < 4; mi++)
#pragma unroll
            for (int ni = 0; ni < 4; ni++) {
                int h0 = n0 + wn * 32 + ni * 8 + (lane & 3) * 2;
                if (h0 < N) {
                    float b0 = bias[(size_t)e * N + h0];
                    float b1 = bias[(size_t)e * N + h0 + 1];
#pragma unroll
                    for (int hh = 0; hh < 2; hh++) {
                        int t = m0 + wm * 64 + mi * 16 + (lane >> 2) + hh * 8;
                        float w = rw[t * NUM_E + e];
                        float2 v;
                        v.x = w * (acc[mi][ni][hh * 2] + b0);
                        v.y = w * (acc[mi][ni][hh * 2 + 1] + b1);
                        *reinterpret_cast<float2*>(&g_oute[((size_t)e * M + t) * N + h0]) = v;
                    }
                }
            }
    }
#undef SM_AH
#undef SM_AL
#undef SM_B
}

extern "C" void kernel_launch(void* const* d_in, const int* in_sizes, int n_in,
                              void* d_out, int out_size) {
    const float* hidden = (const float*)d_in[0];
    const float* rw     = (const float*)d_in[1];
    const int* gub      = (const int*)d_in[2];
    const int* gus      = (const int*)d_in[3];
    const float* gubias = (const float*)d_in[4];
    const int* db       = (const int*)d_in[5];
    const int* ds       = (const int*)d_in[6];
    const float* dbias  = (const float*)d_in[7];
    float* out          = (float*)d_out;

    cudaFuncSetAttribute(gemm_glu<1>, cudaFuncAttributeMaxDynamicSharedMemorySize,
                         SMEM_BYTES);
    cudaFuncSetAttribute(gemm_glu<2>, cudaFuncAttributeMaxDynamicSharedMemorySize,
                         SMEM_BYTES);

    int n4 = DIM_T * DIM_H / 4;
    k_convert<<<(n4 + 255) / 256, 256>>>((const float4*)hidden, n4);

    dim3 g1(DIM_F / 128, DIM_T / 128, NUM_E);
    gemm_glu<1><<<g1, 256, SMEM_BYTES>>>(gub, gus, gubias, nullptr);

    dim3 g2((DIM_H + 127) / 128, DIM_T / 128, NUM_E);
    gemm_glu<2><<<g2, 256, SMEM_BYTES>>>(db, ds, dbias, rw);

    k_reduce<<<(n4 + 255) / 256, 256>>>(out, n4);
}